// round 4
// baseline (speedup 1.0000x reference)
#include <cuda_runtime.h>

#define TPB 256
#define NB  5
#define TILE_ROWS   TPB                  // 256 rows/tile
#define TILE_FLOATS (TILE_ROWS * NB)     // 1280
#define TILE_F4     (TILE_FLOATS / 4)    // 320
#define NBLOCKS     444                  // 148 SMs * 3 resident CTAs (guaranteed by launch_bounds)

__device__ __forceinline__ float f_ex2(float x){ float y; asm("ex2.approx.ftz.f32 %0, %1;" : "=f"(y) : "f"(x)); return y; }
__device__ __forceinline__ float f_lg2(float x){ float y; asm("lg2.approx.ftz.f32 %0, %1;" : "=f"(y) : "f"(x)); return y; }
__device__ __forceinline__ float f_rcp(float x){ float y; asm("rcp.approx.ftz.f32 %0, %1;" : "=f"(y) : "f"(x)); return y; }
__device__ __forceinline__ float f_rsq(float x){ float y; asm("rsqrt.approx.ftz.f32 %0, %1;" : "=f"(y) : "f"(x)); return y; }

__device__ __forceinline__ void solve_row(const float w[25], const float bb[5],
                                          const float xv[NB], float pr[NB])
{
    const float LOG2_5 = 2.3219280948873623f;
    const float EPS2   = 0.14426950408889634f;   // 0.1 / ln2
    const float LN2    = 0.6931471805599453f;

    float q[NB];
    float S = 0.f, Q2 = 0.f;
    #pragma unroll
    for (int j = 0; j < NB; j++) {
        float acc = bb[j];
        #pragma unroll
        for (int k = 0; k < NB; k++) acc = fmaf(xv[k], w[j * NB + k], acc);
        q[j] = acc;
        S  += acc;
        Q2  = fmaf(acc, acc, Q2);
    }
    float rS = f_rcp(S);

    // Sufficient feasibility (Jensen): KL(p||u) <= ln(5*Q2/S^2); e^0.1 ~ 1.10517092
    if (5.0f * Q2 <= 1.1051709f * S * S) {
        #pragma unroll
        for (int j = 0; j < NB; j++) pr[j] = q[j] * rS;
        return;
    }
    // exact test (rare)
    float L[NB], A1 = 0.f;
    #pragma unroll
    for (int j = 0; j < NB; j++) { L[j] = f_lg2(q[j]); A1 = fmaf(L[j], q[j], A1); }
    float KL1 = fmaf(A1, rS, LOG2_5) - f_lg2(S);
    if (KL1 <= EPS2) {
        #pragma unroll
        for (int j = 0; j < NB; j++) pr[j] = q[j] * rS;
        return;
    }
    // Newton on f(t) = KL2(t) - EPS2 (very rare)
    float t = f_rsq(KL1 * 6.9314718055994531f);          // sqrt(EPS2/KL1)
    t = fminf(fmaxf(t, 1e-3f), 0.999f);
    #pragma unroll
    for (int it = 0; it < 5; ++it) {
        float Se = 0.f, A = 0.f, B = 0.f;
        #pragma unroll
        for (int j = 0; j < NB; j++) {
            float z  = t * L[j];
            float e  = f_ex2(z);
            float ze = z * e;
            Se += e;  A += ze;  B = fmaf(z, ze, B);
        }
        float rSe   = f_rcp(Se);
        float fval  = fmaf(A, rSe, LOG2_5 - EPS2) - f_lg2(Se);
        float denom = LN2 * rSe * (B - A * A * rSe);
        t = t - fval * t * f_rcp(denom);
        t = fminf(fmaxf(t, 1e-4f), 1.0f);
    }
    float Se = 0.f, e[NB];
    #pragma unroll
    for (int j = 0; j < NB; j++) { e[j] = f_ex2(t * L[j]); Se += e[j]; }
    float rSe = f_rcp(Se);
    #pragma unroll
    for (int j = 0; j < NB; j++) pr[j] = e[j] * rSe;
}

__global__ __launch_bounds__(TPB, 3)
void klproj_kernel(const float* __restrict__ x,
                   const float* __restrict__ W,
                   const float* __restrict__ b,
                   float* __restrict__ out,
                   int nrows, int ntiles)
{
    __shared__ float sin_[2][TILE_FLOATS];
    __shared__ float sout[2][TILE_FLOATS];

    const int tid   = threadIdx.x;
    const int total = nrows * NB;

    // W/b in registers, amortized over ~ntiles/NBLOCKS tiles
    float w[25], bb[5];
    #pragma unroll
    for (int i = 0; i < 25; i++) w[i]  = __ldg(W + i);
    #pragma unroll
    for (int i = 0; i < 5;  i++) bb[i] = __ldg(b + i);

    const bool has2 = tid < (TILE_F4 - TPB);   // 320-256 = 64 extra float4

    // ---- prologue: stage first tile ----
    int t = blockIdx.x;                         // grid = min(NBLOCKS, ntiles)
    {
        const bool full0 = (t * TILE_FLOATS + TILE_FLOATS) <= total;
        if (full0) {
            const float4* g4 = reinterpret_cast<const float4*>(x) + (size_t)t * TILE_F4;
            float4* s4 = reinterpret_cast<float4*>(sin_[0]);
            s4[tid] = g4[tid];
            if (has2) s4[tid + TPB] = g4[tid + TPB];
        }
    }
    __syncthreads();

    int pbuf = 0;
    for (; t < ntiles; t += NBLOCKS, pbuf ^= 1) {
        const int  fbase = t * TILE_FLOATS;
        const bool full  = (fbase + TILE_FLOATS) <= total;
        const int  tn    = t + NBLOCKS;
        const bool pfn   = (tn < ntiles) && ((tn * TILE_FLOATS + TILE_FLOATS) <= total);

        // prefetch next tile into registers (latency hidden behind compute)
        float4 r0, r1;
        if (pfn) {
            const float4* g4 = reinterpret_cast<const float4*>(x) + (size_t)tn * TILE_F4;
            r0 = g4[tid];
            if (has2) r1 = g4[tid + TPB];
        }

        if (full) {
            float xv[NB], pr[NB];
            #pragma unroll
            for (int j = 0; j < NB; j++) xv[j] = sin_[pbuf][tid * NB + j];  // stride-5: conflict-free
            solve_row(w, bb, xv, pr);
            #pragma unroll
            for (int j = 0; j < NB; j++) sout[pbuf][tid * NB + j] = pr[j];
        } else {
            const int row = fbase / NB + tid;
            if (row < nrows) {
                float xv[NB], pr[NB];
                #pragma unroll
                for (int j = 0; j < NB; j++) xv[j] = x[(size_t)row * NB + j];
                solve_row(w, bb, xv, pr);
                #pragma unroll
                for (int j = 0; j < NB; j++) out[(size_t)row * NB + j] = pr[j];
            }
        }

        // stage prefetched tile into the other input buffer
        if (pfn) {
            float4* s4 = reinterpret_cast<float4*>(sin_[pbuf ^ 1]);
            s4[tid] = r0;
            if (has2) s4[tid + TPB] = r1;
        }

        __syncthreads();   // the ONLY barrier per tile

        // coalesced write-back of this tile's results
        if (full) {
            const float4* so4 = reinterpret_cast<const float4*>(sout[pbuf]);
            float4*       o4  = reinterpret_cast<float4*>(out) + (size_t)t * TILE_F4;
            o4[tid] = so4[tid];
            if (has2) o4[tid + TPB] = so4[tid + TPB];
        }
    }
}

extern "C" void kernel_launch(void* const* d_in, const int* in_sizes, int n_in,
                              void* d_out, int out_size)
{
    const float* x = (const float*)d_in[0];
    const float* W = (const float*)d_in[1];
    const float* b = (const float*)d_in[2];
    if (n_in >= 3 && in_sizes[1] == NB && in_sizes[2] == NB * NB) {
        const float* tmp = W; W = b; b = tmp;
    }
    float* out = (float*)d_out;
    int nrows  = in_sizes[0] / NB;
    int ntiles = (nrows + TILE_ROWS - 1) / TILE_ROWS;
    int blocks = (ntiles < NBLOCKS) ? ntiles : NBLOCKS;
    klproj_kernel<<<blocks, TPB>>>(x, W, b, out, nrows, ntiles);
}

// round 10
// speedup vs baseline: 1.1199x; 1.1199x over previous
#include <cuda_runtime.h>

#define TPB 256
#define NB  5
#define TILE_FLOATS (TPB * NB)        // 1280
#define TILE_F4     (TILE_FLOATS / 4) // 320

__device__ __forceinline__ float f_ex2(float x){ float y; asm("ex2.approx.ftz.f32 %0, %1;" : "=f"(y) : "f"(x)); return y; }
__device__ __forceinline__ float f_lg2(float x){ float y; asm("lg2.approx.ftz.f32 %0, %1;" : "=f"(y) : "f"(x)); return y; }
__device__ __forceinline__ float f_rcp(float x){ float y; asm("rcp.approx.ftz.f32 %0, %1;" : "=f"(y) : "f"(x)); return y; }
__device__ __forceinline__ float f_rsq(float x){ float y; asm("rsqrt.approx.ftz.f32 %0, %1;" : "=f"(y) : "f"(x)); return y; }

__global__ __launch_bounds__(TPB, 7)
void klproj_kernel(const float* __restrict__ x,
                   const float* __restrict__ W,
                   const float* __restrict__ b,
                   float* __restrict__ out,
                   int nrows)
{
    __shared__ float sin_[TILE_FLOATS];  // input staging only
    __shared__ float swb[48];            // W rows padded to 8: [Wj0..Wj4, bj, -, -]

    const int tid   = threadIdx.x;
    const int total = nrows * NB;
    const int fbase = blockIdx.x * TILE_FLOATS;       // max ~10.5M, fits int
    const bool full = (fbase + TILE_FLOATS) <= total;

    // stage W/b padded (one-time, 48 lanes)
    if (tid < 48) {
        int j = tid >> 3, k = tid & 7;
        float v = 0.f;
        if (k < 5)       v = W[j * 5 + k];
        else if (k == 5) v = b[j];
        swb[tid] = v;
    }

    // ---- stage input tile: coalesced float4 ----
    if (full) {
        const float4* g4 = reinterpret_cast<const float4*>(x) + (size_t)blockIdx.x * TILE_F4;
        float4*       s4 = reinterpret_cast<float4*>(sin_);
        s4[tid] = g4[tid];
        if (tid < TILE_F4 - TPB) s4[tid + TPB] = g4[tid + TPB];
    }
    __syncthreads();   // the only barrier

    const int row = fbase / NB + tid;
    if (row >= nrows) return;

    // ---- row load: stride-5 scalar LDS (gcd(5,32)=1 -> conflict-free) ----
    float xv[NB];
    if (full) {
        #pragma unroll
        for (int j = 0; j < NB; j++) xv[j] = sin_[tid * NB + j];
    } else {
        #pragma unroll
        for (int j = 0; j < NB; j++) xv[j] = x[(size_t)row * NB + j];
    }

    // ---- GEMV: 2 vector LDS + 5 FMA per output component ----
    float q[NB];
    float S = 0.f;
    #pragma unroll
    for (int j = 0; j < NB; j++) {
        float4 wj = *reinterpret_cast<const float4*>(&swb[j * 8]);      // LDS.128 broadcast
        float2 wb = *reinterpret_cast<const float2*>(&swb[j * 8 + 4]);  // LDS.64  broadcast (W4, bj)
        float acc = wb.y;
        acc = fmaf(xv[0], wj.x, acc);
        acc = fmaf(xv[1], wj.y, acc);
        acc = fmaf(xv[2], wj.z, acc);
        acc = fmaf(xv[3], wj.w, acc);
        acc = fmaf(xv[4], wb.x, acc);
        q[j] = acc;
        S += acc;
    }
    float rS = f_rcp(S);

    const float LOG2_5 = 2.3219280948873623f;
    const float EPS2   = 0.14426950408889634f;   // 0.1 / ln2
    const float LN2    = 0.6931471805599453f;

    // ---- exact feasibility (uniform cost: no divergence trap) ----
    float L[NB], A1 = 0.f;
    #pragma unroll
    for (int j = 0; j < NB; j++) { L[j] = f_lg2(q[j]); A1 = fmaf(L[j], q[j], A1); }
    float KL1 = fmaf(A1, rS, LOG2_5) - f_lg2(S);

    float p[NB];
    if (KL1 <= EPS2) {
        #pragma unroll
        for (int j = 0; j < NB; j++) p[j] = q[j] * rS;
    } else {
        // Newton on f(t) = KL2(t) - EPS2 (rare)
        float t = f_rsq(KL1 * 6.9314718055994531f);      // sqrt(EPS2/KL1)
        t = fminf(fmaxf(t, 1e-3f), 0.999f);
        #pragma unroll
        for (int it = 0; it < 5; ++it) {
            float Se = 0.f, A = 0.f, B = 0.f;
            #pragma unroll
            for (int j = 0; j < NB; j++) {
                float z  = t * L[j];
                float e  = f_ex2(z);
                float ze = z * e;
                Se += e;  A += ze;  B = fmaf(z, ze, B);
            }
            float rSe   = f_rcp(Se);
            float fval  = fmaf(A, rSe, LOG2_5 - EPS2) - f_lg2(Se);
            float denom = LN2 * rSe * (B - A * A * rSe);
            t = t - fval * t * f_rcp(denom);
            t = fminf(fmaxf(t, 1e-4f), 1.0f);
        }
        float Se = 0.f, e[NB];
        #pragma unroll
        for (int j = 0; j < NB; j++) { e[j] = f_ex2(t * L[j]); Se += e[j]; }
        float rSe = f_rcp(Se);
        #pragma unroll
        for (int j = 0; j < NB; j++) p[j] = e[j] * rSe;
    }

    // ---- direct scalar stores (no barrier, no out staging) ----
    float* orow = out + (size_t)row * NB;
    #pragma unroll
    for (int j = 0; j < NB; j++) orow[j] = p[j];
}

extern "C" void kernel_launch(void* const* d_in, const int* in_sizes, int n_in,
                              void* d_out, int out_size)
{
    const float* x = (const float*)d_in[0];
    const float* W = (const float*)d_in[1];
    const float* b = (const float*)d_in[2];
    if (n_in >= 3 && in_sizes[1] == NB && in_sizes[2] == NB * NB) {
        const float* tmp = W; W = b; b = tmp;
    }
    float* out = (float*)d_out;
    int nrows  = in_sizes[0] / NB;
    int blocks = (nrows + TPB - 1) / TPB;
    klproj_kernel<<<blocks, TPB>>>(x, W, b, out, nrows);
}